// round 17
// baseline (speedup 1.0000x reference)
#include <cuda_runtime.h>
#include <cuda_bf16.h>
#include <cstdint>

#define HIDDEN 512
#define MAX_LEN 4096
#define BATCH 32

// Scratch: v[b][h] = sum_o hidden[b][o] * W[o][h]   (Wᵀ·hidden per batch)
__device__ float4 g_v4[BATCH * (HIDDEN / 4)];  // 64 KB

// ---------------------------------------------------------------------------
// Kernel 1: v[b] = hiddenᵀ[b] @ W.  (R8 math — measured floor ~5.9us.)
// Grid: (16 batch-pairs x 16 h-chunks) = 256 blocks (one wave), 512 threads.
// Fires the PDL trigger at entry so the dependent energy kernel launches
// immediately and overlaps its enc prefetch with this kernel's execution.
// ---------------------------------------------------------------------------
__global__ void v_kernel(const float* __restrict__ hidden,
                         const float* __restrict__ W) {
    cudaTriggerProgrammaticLaunchCompletion();   // let energy launch now

    __shared__ float  hs[2][HIDDEN];      // 2 batches of hidden
    __shared__ float4 part[2][16][8];     // [batch][warp][h-quad]

    const int bg = blockIdx.x >> 4;       // batch pair 0..15
    const int hc = blockIdx.x & 15;       // h-chunk 0..15
    const int t  = threadIdx.x;           // 0..511

    // 2*512 floats = 256 float4s.
    if (t < 256)
        reinterpret_cast<float4*>(&hs[0][0])[t] =
            reinterpret_cast<const float4*>(hidden + bg * 2 * HIDDEN)[t];
    __syncthreads();

    const int og = t >> 3;                // o-group 0..63 (8 rows each)
    const int j  = t & 7;                 // local h-quad 0..7
    const int jq = hc * 8 + j;            // global h-quad 0..127

    const float4* __restrict__ W4 = reinterpret_cast<const float4*>(W);

    float4 w[8];
    const int o0 = og * 8;
#pragma unroll
    for (int o = 0; o < 8; o++)
        w[o] = W4[(size_t)(o0 + o) * 128 + jq];

    float4 acc[2];
#pragma unroll
    for (int bi = 0; bi < 2; bi++) acc[bi] = make_float4(0.f, 0.f, 0.f, 0.f);

#pragma unroll
    for (int o = 0; o < 8; o++) {
#pragma unroll
        for (int bi = 0; bi < 2; bi++) {
            const float hv = hs[bi][o0 + o];
            acc[bi].x += hv * w[o].x;
            acc[bi].y += hv * w[o].y;
            acc[bi].z += hv * w[o].z;
            acc[bi].w += hv * w[o].w;
        }
    }

    // Warp holds 4 o-groups (lane>>3) x 8 quads (lane&7): fold o-groups.
#pragma unroll
    for (int off = 8; off <= 16; off <<= 1) {
#pragma unroll
        for (int bi = 0; bi < 2; bi++) {
            acc[bi].x += __shfl_xor_sync(0xFFFFFFFFu, acc[bi].x, off);
            acc[bi].y += __shfl_xor_sync(0xFFFFFFFFu, acc[bi].y, off);
            acc[bi].z += __shfl_xor_sync(0xFFFFFFFFu, acc[bi].z, off);
            acc[bi].w += __shfl_xor_sync(0xFFFFFFFFu, acc[bi].w, off);
        }
    }

    const int lane = t & 31;
    const int warp = t >> 5;
    if (lane < 8) {
#pragma unroll
        for (int bi = 0; bi < 2; bi++) part[bi][warp][lane] = acc[bi];
    }
    __syncthreads();

    // Tail fold: 32 threads, each folds 8 of 16 warps; halves combined via
    // one xor-16 shuffle.
    if (t < 32) {
        const int half = t >> 4;          // 0 or 1: warps [0..7] or [8..15]
        const int bi   = (t >> 3) & 1;
        const int jj   = t & 7;
        float4 s = part[bi][half * 8][jj];
#pragma unroll
        for (int wi = 1; wi < 8; wi++) {
            const float4 p = part[bi][half * 8 + wi][jj];
            s.x += p.x; s.y += p.y; s.z += p.z; s.w += p.w;
        }
        s.x += __shfl_xor_sync(0xFFFFFFFFu, s.x, 16);
        s.y += __shfl_xor_sync(0xFFFFFFFFu, s.y, 16);
        s.z += __shfl_xor_sync(0xFFFFFFFFu, s.z, 16);
        s.w += __shfl_xor_sync(0xFFFFFFFFu, s.w, 16);
        if (half == 0)
            g_v4[(bg * 2 + bi) * 128 + hc * 8 + jj] = s;
    }
}

// ---------------------------------------------------------------------------
// Kernel 2 (PDL consumer of v, producer for sumscale): each block handles 16
// consecutive rows (32 KB of contiguous enc). Prefetch is cp.async.cg into
// smem (register-free, so 32 KB/block stays in flight while the block waits
// at the grid sync) -> the DRAM stream runs deep DURING v_kernel instead of
// idling. After sync: dot each row with v[b] (plain __ldg — visibility
// guaranteed by PDL), warp-reduce, store exp(e) (bias dropped: constant in
// l under softmax; no max-sub: |e| << 88, validated R7-R15). NO atomics.
// ---------------------------------------------------------------------------
__global__ void energy_kernel(const float* __restrict__ enc,
                              float* __restrict__ out) {
    __shared__ float4 tile[16 * 128];     // 16 rows x 2 KB = 32 KB

    const int t = threadIdx.x;            // 0..255

    // 2048 16B-chunks; 8 cp.async per thread, fully coalesced.
    const float4* __restrict__ src =
        reinterpret_cast<const float4*>(enc) + (size_t)blockIdx.x * 16 * 128;
    const unsigned sbase = (unsigned)__cvta_generic_to_shared(tile);
#pragma unroll
    for (int i = 0; i < 8; i++) {
        const int idx = i * 256 + t;
        asm volatile("cp.async.cg.shared.global [%0], [%1], 16;\n"
                     :: "r"(sbase + idx * 16), "l"(src + idx));
    }
    asm volatile("cp.async.commit_group;\n" ::: "memory");

    cudaGridDependencySynchronize();      // v grid complete + g_v4 visible

    asm volatile("cp.async.wait_group 0;\n" ::: "memory");
    __syncthreads();

    const int warp = t >> 5;
    const int lane = t & 31;

#pragma unroll
    for (int rr = 0; rr < 2; rr++) {
        const int row = warp * 2 + rr;               // 0..15
        const int r   = blockIdx.x * 16 + row;       // global row = l*32+b
        const int b   = r & (BATCH - 1);
        const int l   = r >> 5;

        const float4* __restrict__ v4 = g_v4 + b * (HIDDEN / 4);

        float acc = 0.f;
#pragma unroll
        for (int k = 0; k < 4; k++) {
            const float4 a = tile[row * 128 + lane + k * 32];
            const float4 w = __ldg(&v4[lane + k * 32]);
            acc += a.x * w.x + a.y * w.y + a.z * w.z + a.w * w.w;
        }
#pragma unroll
        for (int off = 16; off; off >>= 1)
            acc += __shfl_xor_sync(0xFFFFFFFFu, acc, off);

        if (lane == 0) out[(size_t)b * MAX_LEN + l] = __expf(acc);
    }

    // Stores are program-ordered before the trigger -> visible to sumscale.
    cudaTriggerProgrammaticLaunchCompletion();
}

// ---------------------------------------------------------------------------
// Kernel 3 (PDL consumer): per-row sum + scale (normalize half of softmax;
// exp already applied). Syncs FIRST ('out' is produced by energy).
// 32 blocks x 1024 threads, one float4 per thread.
// ---------------------------------------------------------------------------
__global__ void sumscale_kernel(float* __restrict__ out) {
    cudaGridDependencySynchronize();   // all energy blocks have stored

    __shared__ float red[32];

    const int b = blockIdx.x;
    const int t = threadIdx.x;
    float4* __restrict__ row4 =
        reinterpret_cast<float4*>(out) + (size_t)b * (MAX_LEN / 4);

    float4 x = row4[t];

    float s = x.x + x.y + x.z + x.w;
#pragma unroll
    for (int o = 16; o; o >>= 1)
        s += __shfl_xor_sync(0xFFFFFFFFu, s, o);
    if ((t & 31) == 0) red[t >> 5] = s;
    __syncthreads();
    if (t < 32) {
        float ss = red[t];
#pragma unroll
        for (int o = 16; o; o >>= 1)
            ss += __shfl_xor_sync(0xFFFFFFFFu, ss, o);
        if (t == 0) red[0] = ss;
    }
    __syncthreads();
    const float inv = 1.0f / red[0];

    x.x *= inv; x.y *= inv; x.z *= inv; x.w *= inv;
    row4[t] = x;
}

// ---------------------------------------------------------------------------
extern "C" void kernel_launch(void* const* d_in, const int* in_sizes, int n_in,
                              void* d_out, int out_size) {
    const float* hidden = (const float*)d_in[0];   // [1, 32, 512]
    const float* enc    = (const float*)d_in[1];   // [4096, 32, 512]
    const float* W      = (const float*)d_in[2];   // [512, 512]
    // d_in[3] = bias: provably irrelevant (constant shift under softmax)
    float* out = (float*)d_out;                    // [32, 1, 4096]

    v_kernel<<<256, 512>>>(hidden, W);

    cudaLaunchAttribute attr[1];
    attr[0].id = cudaLaunchAttributeProgrammaticStreamSerialization;
    attr[0].val.programmaticStreamSerializationAllowed = 1;

    // Energy: PDL consumer of v; cp.async prefetch keeps DRAM busy during v.
    const int rows = MAX_LEN * BATCH;              // 131072
    cudaLaunchConfig_t cfg = {};
    cfg.gridDim  = dim3(rows / 16);                // 8192 blocks
    cfg.blockDim = dim3(256);
    cfg.attrs    = attr;
    cfg.numAttrs = 1;
    cudaLaunchKernelEx(&cfg, energy_kernel, enc, out);

    // Sumscale: PDL consumer of energy (releases on post-store triggers).
    cudaLaunchConfig_t cfg2 = {};
    cfg2.gridDim  = dim3(BATCH);
    cfg2.blockDim = dim3(MAX_LEN / 4);
    cfg2.attrs    = attr;
    cfg2.numAttrs = 1;
    cudaLaunchKernelEx(&cfg2, sumscale_kernel, out);
}